// round 1
// baseline (speedup 1.0000x reference)
#include <cuda_runtime.h>
#include <cuda_bf16.h>

#define F_DIM 35
#define T_PAD 520      // pad so lp[0],lp[1],lp[2] land in different banks
#define E_MAX 256
#define NEGC (-1e30f)

__device__ float g_partials[4096];

__global__ __launch_bounds__(256, 4) void sctc_fwd_kernel(
    const float* __restrict__ logits,        // (B,T,F)
    const float* __restrict__ blank_logit,   // (1,)
    const int*   __restrict__ targets,       // (B,S,F)
    const int*   __restrict__ input_lengths, // (B,)
    const int*   __restrict__ target_lengths,// (B,)
    int B, int T, int S)
{
    __shared__ float lp[3][T_PAD];   // per-frame log-softmax of {-x, x, blank}
    __shared__ float A[2][E_MAX];    // alpha ping-pong

    const int bx  = blockIdx.x;
    const int b   = bx / F_DIM;
    const int f   = bx - b * F_DIM;
    const int tid = threadIdx.x;
    const int E   = 2 * S + 1;

    const float bl = blank_logit[0];

    // ---- Precompute 3-class log-softmax for every frame of this (b,f) ----
    for (int t = tid; t < T; t += blockDim.x) {
        float x   = logits[(b * T + t) * F_DIM + f];
        float m   = fmaxf(fabsf(x), bl);
        float lse = m + __logf(__expf(-x - m) + __expf(x - m) + __expf(bl - m));
        lp[0][t] = -x - lse;   // label == 0 (absent)
        lp[1][t] =  x - lse;   // label == 1 (present)
        lp[2][t] = bl - lse;   // blank
    }

    // ---- Per-state transition structure ----
    const int s = tid;
    const float* lpp = &lp[2][0];   // default: blank row (even states)
    bool skip = false;              // a2 allowed (s>=2, odd, labels differ)
    if (s < E && (s & 1)) {
        int k   = s >> 1;
        int lab = targets[(b * S + k) * F_DIM + f];
        lpp = &lp[lab][0];
        if (k >= 1) {
            int labp = targets[(b * S + k - 1) * F_DIM + f];
            skip = (lab != labp);
        }
    }
    __syncthreads();

    // ---- alpha init at t=0 ----
    if (s < E) A[0][s] = (s < 2) ? lpp[0] : NEGC;
    __syncthreads();

    const int Tin = input_lengths[b];
    int cur = 0;

    // ---- forward recursion ----
    for (int t = 1; t < Tin; ++t) {
        if (s < E) {
            float a0 = A[cur][s];
            float a1 = (s >= 1) ? A[cur][s - 1] : NEGC;
            float a2 = skip     ? A[cur][s - 2] : NEGC;
            float m  = fmaxf(fmaxf(a0, a1), a2);
            float r  = m + __logf(__expf(a0 - m) + __expf(a1 - m) + __expf(a2 - m))
                       + lpp[t];
            A[cur ^ 1][s] = r;
        }
        cur ^= 1;
        __syncthreads();
    }

    // ---- finalize: lse over last two states of the valid path ----
    if (tid == 0) {
        int   Lt  = target_lengths[b];
        float aL  = A[cur][2 * Lt];
        float aL1 = A[cur][2 * Lt - 1];
        float m   = fmaxf(aL, aL1);
        float ll  = m + __logf(__expf(aL - m) + __expf(aL1 - m));
        float loss = -ll;
        if (loss > 0.5e30f) loss = 0.0f;   // zero_infinity
        g_partials[bx] = loss / (float)Lt;
    }
}

// Deterministic fixed-order reduction over the 560 partials.
__global__ void sctc_reduce_kernel(float* __restrict__ out, int n, float inv)
{
    float sv = 0.0f;
    for (int i = threadIdx.x; i < n; i += 32) sv += g_partials[i];
    #pragma unroll
    for (int o = 16; o; o >>= 1) sv += __shfl_down_sync(0xffffffffu, sv, o);
    if (threadIdx.x == 0) out[0] = sv * inv;
}

extern "C" void kernel_launch(void* const* d_in, const int* in_sizes, int n_in,
                              void* d_out, int out_size)
{
    const float* logits  = (const float*)d_in[0];
    const float* blankl  = (const float*)d_in[1];
    const int*   targets = (const int*)d_in[2];
    const int*   in_len  = (const int*)d_in[3];
    const int*   tg_len  = (const int*)d_in[4];

    const int B = in_sizes[3];
    const int T = in_sizes[0] / (B * F_DIM);
    const int S = in_sizes[2] / (B * F_DIM);
    const int nblk = B * F_DIM;

    sctc_fwd_kernel<<<nblk, 256>>>(logits, blankl, targets, in_len, tg_len, B, T, S);
    sctc_reduce_kernel<<<1, 32>>>((float*)d_out, nblk, 1.0f / (float)nblk);
}

// round 2
// speedup vs baseline: 1.3782x; 1.3782x over previous
#include <cuda_runtime.h>
#include <cuda_bf16.h>

#define F_DIM 35
#define T_MAX 512
#define NEGC  (-1e30f)
#define LOG2E 1.4426950408889634f

__device__ float g_partials[1024];
__device__ int   g_count = 0;

__device__ __forceinline__ float ex2f(float x) {
    float r; asm("ex2.approx.ftz.f32 %0, %1;" : "=f"(r) : "f"(x)); return r;
}
__device__ __forceinline__ float lg2f(float x) {
    float r; asm("lg2.approx.ftz.f32 %0, %1;" : "=f"(r) : "f"(x)); return r;
}

// 256 threads/CTA: warps 0-3 = even states (blanks, 2-term lse),
//                  warps 4-7 = odd states (labels, 3-term lse via median sort).
// Everything in log2 domain; convert by ln2 at the very end.
__global__ __launch_bounds__(256, 4) void sctc_fused_kernel(
    const float* __restrict__ logits,        // (B,T,F)
    const float* __restrict__ blank_logit,   // (1,)
    const int*   __restrict__ targets,       // (B,S,F)
    const int*   __restrict__ input_lengths, // (B,)
    const int*   __restrict__ target_lengths,// (B,)
    float* __restrict__ out,
    int B, int T, int S)
{
    __shared__ float lp2[3][T_MAX];   // log2-softmax of {absent, present, blank}
    __shared__ float Ae[2][128];      // alpha, even states:  Ae[buf][i] = a[2i]
    __shared__ float Ao[2][128];      // alpha, odd  states:  Ao[buf][k] = a[2k+1]

    const int bx  = blockIdx.x;
    const int b   = bx / F_DIM;
    const int f   = bx - b * F_DIM;
    const int tid = threadIdx.x;

    const float ub = blank_logit[0] * LOG2E;

    // ---- 3-class log2-softmax for every frame of this (b,f) ----
    for (int t = tid; t < T; t += 256) {
        float u  = logits[(b * T + t) * F_DIM + f] * LOG2E;
        float m  = fmaxf(fabsf(u), ub);
        float ls = m + lg2f(ex2f(-u - m) + ex2f(u - m) + ex2f(ub - m));
        lp2[0][t] = -u - ls;
        lp2[1][t] =  u - ls;
        lp2[2][t] = ub - ls;
    }

    const bool evenHalf = (tid < 128);
    const int  i = tid;            // even-state index: state s = 2i,   valid i <= S
    const int  k = tid - 128;      // odd-state index:  state s = 2k+1, valid k <  S

    const float* lpp = &lp2[2][0];   // even: blank row
    bool skip = false;
    bool act;
    if (evenHalf) {
        act = (i <= S);
    } else {
        act = (k < S);
        if (act) {
            int lab = targets[(b * S + k) * F_DIM + f];
            lpp = &lp2[lab][0];
            if (k >= 1) skip = (lab != targets[(b * S + k - 1) * F_DIM + f]);
        }
    }
    __syncthreads();

    // ---- alpha init at t=0 (in shared AND register carry a0) ----
    float a0 = NEGC;
    if (act) {
        if (evenHalf) { a0 = (i == 0) ? lpp[0] : NEGC; Ae[0][i] = a0; }
        else          { a0 = (k == 0) ? lpp[0] : NEGC; Ao[0][k] = a0; }
    }
    __syncthreads();

    const int Tin = input_lengths[b];
    int cur = 0;

    // ---- forward recursion, one barrier per frame ----
    for (int t = 1; t < Tin; ++t) {
        int nxt = cur ^ 1;
        if (act) {
            if (evenHalf) {
                // 2-term lse: states 2i read a[2i] (reg), a[2i-1] = Ao[i-1]
                float a1 = (i >= 1) ? Ao[cur][i - 1] : NEGC;
                float m  = fmaxf(a0, a1);
                float mn = fminf(a0, a1);
                a0 = m + lg2f(1.0f + ex2f(mn - m)) + lpp[t];
                Ae[nxt][i] = a0;
            } else {
                // 3-term lse: a[2k+1] (reg), a[2k] = Ae[k], a[2k-1] = Ao[k-1]
                float a1 = Ae[cur][k];
                float a2 = (skip) ? Ao[cur][k - 1] : NEGC;
                float mx01 = fmaxf(a0, a1);
                float mn01 = fminf(a0, a1);
                float m    = fmaxf(mx01, a2);
                float mid  = fminf(mx01, fmaxf(mn01, a2));
                float lo   = fminf(mn01, a2);
                a0 = m + lg2f(1.0f + ex2f(mid - m) + ex2f(lo - m)) + lpp[t];
                Ao[nxt][k] = a0;
            }
        }
        cur = nxt;
        __syncthreads();
    }

    // ---- finalize + fused deterministic reduction ----
    bool isLast = false;
    if (tid == 0) {
        int   Lt  = target_lengths[b];
        float aL  = Ae[cur][Lt];        // alpha[2L]
        float aL1 = Ao[cur][Lt - 1];    // alpha[2L-1]
        float m   = fmaxf(aL, aL1);
        float mn  = fminf(aL, aL1);
        float ll2 = m + lg2f(1.0f + ex2f(mn - m));
        float loss = -ll2 * 0.6931471805599453f;
        if (loss > 0.5e30f) loss = 0.0f;           // zero_infinity
        g_partials[bx] = loss / (float)Lt;
        __threadfence();
        int old = atomicAdd(&g_count, 1);
        isLast = (old == (int)gridDim.x - 1);
    }
    if (tid < 32) {
        int last = __shfl_sync(0xffffffffu, isLast ? 1 : 0, 0);
        if (last) {
            int   n  = gridDim.x;
            float sv = 0.0f;
            for (int j = tid; j < n; j += 32) sv += g_partials[j];
            #pragma unroll
            for (int o = 16; o; o >>= 1) sv += __shfl_down_sync(0xffffffffu, sv, o);
            if (tid == 0) {
                out[0] = sv / (float)n;
                g_count = 0;               // reset for next graph replay
            }
        }
    }
}

extern "C" void kernel_launch(void* const* d_in, const int* in_sizes, int n_in,
                              void* d_out, int out_size)
{
    const float* logits  = (const float*)d_in[0];
    const float* blankl  = (const float*)d_in[1];
    const int*   targets = (const int*)d_in[2];
    const int*   in_len  = (const int*)d_in[3];
    const int*   tg_len  = (const int*)d_in[4];

    const int B = in_sizes[3];
    const int T = in_sizes[0] / (B * F_DIM);
    const int S = in_sizes[2] / (B * F_DIM);
    const int nblk = B * F_DIM;

    sctc_fused_kernel<<<nblk, 256>>>(logits, blankl, targets, in_len, tg_len,
                                     (float*)d_out, B, T, S);
}

// round 3
// speedup vs baseline: 1.6769x; 1.2167x over previous
#include <cuda_runtime.h>
#include <cuda_bf16.h>

#define F_DIM 35
#define T_MAX 512
#define NEGC  (-1e30f)
#define LOG2E 1.4426950408889634f
#define LN2   0.6931471805599453f

__device__ float g_partials[1024];
__device__ int   g_count = 0;

__device__ __forceinline__ float ex2f(float x) {
    float r; asm("ex2.approx.ftz.f32 %0, %1;" : "=f"(r) : "f"(x)); return r;
}
__device__ __forceinline__ float lg2f(float x) {
    float r; asm("lg2.approx.ftz.f32 %0, %1;" : "=f"(r) : "f"(x)); return r;
}

// 128 threads/CTA; thread k owns extended states 2k (blank) and 2k+1 (label k).
// alpha lives entirely in registers; the only cross-thread value per step is
// alpha_odd[k-1], delivered by one shfl_up (+ tiny mailbox at warp boundaries).
__global__ __launch_bounds__(128, 8) void sctc_fused_kernel(
    const float* __restrict__ logits,        // (B,T,F)
    const float* __restrict__ blank_logit,   // (1,)
    const int*   __restrict__ targets,       // (B,S,F)
    const int*   __restrict__ input_lengths, // (B,)
    const int*   __restrict__ target_lengths,// (B,)
    float* __restrict__ out,
    int B, int T, int S)
{
    __shared__ float lp2[3][T_MAX];  // log2-softmax rows: absent / present / blank
    __shared__ float mail[2][4];     // warp-boundary alpha_odd, double-buffered
    __shared__ float AeF[128];       // final even alphas
    __shared__ float AoF[128];       // final odd alphas

    const int bx   = blockIdx.x;
    const int b    = bx / F_DIM;
    const int f    = bx - b * F_DIM;
    const int tid  = threadIdx.x;
    const int lane = tid & 31;
    const int w    = tid >> 5;

    const float ub = blank_logit[0] * LOG2E;

    // ---- 3-class log2-softmax for every frame of this (b,f) ----
    for (int t = tid; t < T; t += 128) {
        float u  = logits[(b * T + t) * F_DIM + f] * LOG2E;
        float m  = fmaxf(fabsf(u), ub);
        float ls = m + lg2f(ex2f(-u - m) + ex2f(u - m) + ex2f(ub - m));
        lp2[0][t] = -u - ls;
        lp2[1][t] =  u - ls;
        lp2[2][t] = ub - ls;
    }

    // ---- transition structure for the odd (label) state of this thread ----
    const int k = tid;
    bool skip = false;
    const float* lpl = &lp2[2][0];
    if (k < S) {
        int lab = targets[(b * S + k) * F_DIM + f];
        lpl = &lp2[lab][0];
        if (k >= 1) skip = (lab != targets[(b * S + k - 1) * F_DIM + f]);
    }
    const float* lpb = &lp2[2][0];

    __syncthreads();

    // ---- alpha init at t=0 ----
    float ae = NEGC, ao = NEGC;
    if (k == 0) { ae = lpb[0]; ao = lpl[0]; }
    if (lane == 31) mail[0][w] = ao;
    __syncthreads();

    const int Tin = input_lengths[b];

    // ---- forward recursion: one shfl + one barrier per frame ----
    for (int t = 1; t < Tin; ++t) {
        float ao_prev = __shfl_up_sync(0xffffffffu, ao, 1);
        if (lane == 0) ao_prev = (w == 0) ? NEGC : mail[(t - 1) & 1][w - 1];

        float lpb_t = lpb[t];
        float lpl_t = lpl[t];

        // even state 2k: lse2(alpha[2k], alpha[2k-1])
        float m2 = fmaxf(ae, ao_prev);
        float n2 = fminf(ae, ao_prev);
        float ae_new = m2 + lg2f(1.0f + ex2f(n2 - m2)) + lpb_t;

        // odd state 2k+1: lse3(alpha[2k+1], alpha[2k], skip ? alpha[2k-1] : -inf)
        float a2   = skip ? ao_prev : NEGC;
        float mx01 = fmaxf(ao, ae);
        float mn01 = fminf(ao, ae);
        float m3   = fmaxf(mx01, a2);
        float mid  = fminf(mx01, fmaxf(mn01, a2));
        float lo   = fminf(mn01, a2);
        float ao_new = m3 + lg2f(1.0f + ex2f(mid - m3) + ex2f(lo - m3)) + lpl_t;

        ae = ae_new;
        ao = ao_new;
        if (lane == 31) mail[t & 1][w] = ao;
        __syncthreads();
    }

    // ---- spill final alphas so thread 0 can finalize ----
    AeF[tid] = ae;
    AoF[tid] = ao;
    __syncthreads();

    bool isLast = false;
    if (tid == 0) {
        int   Lt  = target_lengths[b];
        float aL  = AeF[Lt];         // alpha[2L]
        float aL1 = AoF[Lt - 1];     // alpha[2L-1]
        float m   = fmaxf(aL, aL1);
        float mn  = fminf(aL, aL1);
        float ll2 = m + lg2f(1.0f + ex2f(mn - m));
        float loss = -ll2 * LN2;
        if (loss > 0.5e30f) loss = 0.0f;           // zero_infinity
        g_partials[bx] = loss / (float)Lt;
        __threadfence();
        int old = atomicAdd(&g_count, 1);
        isLast = (old == (int)gridDim.x - 1);
    }
    if (tid < 32) {
        int last = __shfl_sync(0xffffffffu, isLast ? 1 : 0, 0);
        if (last) {
            int   n  = gridDim.x;
            float sv = 0.0f;
            for (int j = tid; j < n; j += 32) sv += g_partials[j];
            #pragma unroll
            for (int o = 16; o; o >>= 1) sv += __shfl_down_sync(0xffffffffu, sv, o);
            if (tid == 0) {
                out[0] = sv / (float)n;
                g_count = 0;               // reset for next graph replay
            }
        }
    }
}

extern "C" void kernel_launch(void* const* d_in, const int* in_sizes, int n_in,
                              void* d_out, int out_size)
{
    const float* logits  = (const float*)d_in[0];
    const float* blankl  = (const float*)d_in[1];
    const int*   targets = (const int*)d_in[2];
    const int*   in_len  = (const int*)d_in[3];
    const int*   tg_len  = (const int*)d_in[4];

    const int B = in_sizes[3];
    const int T = in_sizes[0] / (B * F_DIM);
    const int S = in_sizes[2] / (B * F_DIM);
    const int nblk = B * F_DIM;

    sctc_fused_kernel<<<nblk, 128>>>(logits, blankl, targets, in_len, tg_len,
                                     (float*)d_out, B, T, S);
}